// round 3
// baseline (speedup 1.0000x reference)
#include <cuda_runtime.h>

// Problem shape (fixed): x[B=8][C=64][T=256][V=128], W[64][64], a[128][1]
// out[b][f][t][v] = elu(diag[b,v,t] * Wh[b,v,t,f])
//   Wh[b,v,t,f] = sum_c x[b,c,t,v] * W[c,f]
//   s1[v] = Wh[v,:]·a1 ; s2[v] = Wh[v,:]·a2   (per b,t)
//   diag[v] = exp(L(s1[v]+s2[v])) / sum_j exp(L(s1[v]+s2[j])),  L = leaky(0.2)

#define ALPHA 0.2f
constexpr int Bn = 8, Cn = 64, Tn = 256, Vn = 128, Fn = 64;

// ---- f32x2 packed FMA (Blackwell FFMA2: 2x fp32 FMA throughput per instr) ----
__device__ __forceinline__ unsigned long long ffma2(unsigned long long a,
                                                    unsigned long long b,
                                                    unsigned long long c) {
    unsigned long long d;
    asm("fma.rn.f32x2 %0, %1, %2, %3;" : "=l"(d) : "l"(a), "l"(b), "l"(c));
    return d;
}
__device__ __forceinline__ unsigned long long splat2(float x) {
    unsigned long long d;
    asm("mov.b64 %0, {%1, %1};" : "=l"(d) : "f"(x));
    return d;
}
__device__ __forceinline__ float2 unpack2(unsigned long long v) {
    float2 p;
    asm("mov.b64 {%0, %1}, %2;" : "=f"(p.x), "=f"(p.y) : "l"(v));
    return p;
}

// ---- dynamic smem layout (offsets in floats; all 16B-aligned) ----
#define OFF_WS   0        // W[c][f]          64*64
#define OFF_XS   4096     // x[c][v]          64*128
#define OFF_WHS  12288    // Wh[f][v]         64*128
#define OFF_A1   20480    // a1[f]            64
#define OFF_A2   20544    // a2[f]            64
#define OFF_S1   20608    // s1[v]            128
#define OFF_S2   20736    // s2[v]            128
#define OFF_DENP 20864    // den partials     2*128
#define OFF_DIAG 21120    // diag[v]          128
#define SMEM_FLOATS 21248 // 84,992 bytes

extern __shared__ float smem[];

__global__ __launch_bounds__(256, 2)
void GraphAttentionLayer4D_78082505441863_kernel(
    const float* __restrict__ x, const float* __restrict__ W,
    const float* __restrict__ a, float* __restrict__ out)
{
    const int t   = blockIdx.x;
    const int b   = blockIdx.y;
    const int tid = threadIdx.x;

    float* Ws  = smem + OFF_WS;
    float* xs  = smem + OFF_XS;
    float* Whs = smem + OFF_WHS;

    // ---- stage W (L2-resident, 16KB) ----
    {
        const float4* Wg  = (const float4*)W;
        float4*       Ws4 = (float4*)Ws;
        #pragma unroll
        for (int i = tid; i < (Cn * Fn) / 4; i += 256) Ws4[i] = Wg[i];
    }
    // ---- stage x slice x[b, :, t, :] -> xs[c][v]  (64 rows of 512B, coalesced) ----
    {
        const float4* xg  = (const float4*)x;
        float4*       xs4 = (float4*)xs;
        #pragma unroll
        for (int i = tid; i < (Cn * Vn) / 4; i += 256) {
            int c = i >> 5, v4 = i & 31;  // 32 float4 per row
            xs4[i] = xg[((size_t)(b * Cn + c) * Tn + t) * (Vn / 4) + v4];
        }
    }
    if (tid < 128) {
        float av = a[tid];
        if (tid < 64) smem[OFF_A1 + tid] = av;
        else          smem[OFF_A2 + tid - 64] = av;
    }
    __syncthreads();

    // ---- GEMM: Wh[v][f] = sum_c xs[c][v] * Ws[c][f] ----
    // 256 threads = 32 v-threads x 8 f-threads; each thread: 4v x 8f tile,
    // f packed pairwise into f32x2 accumulators (16 FFMA2 per c per thread).
    const int vt = tid & 31, ft = tid >> 5;
    const int v0 = vt * 4,  f0 = ft * 8;

    unsigned long long acc[4][4];
    #pragma unroll
    for (int i = 0; i < 4; i++)
        #pragma unroll
        for (int j = 0; j < 4; j++) acc[i][j] = 0ull;

    #pragma unroll 8
    for (int c = 0; c < Cn; c++) {
        float4 xv = *(const float4*)(xs + c * Vn + v0);                 // LDS.128, conflict-free
        const ulonglong2* wr = (const ulonglong2*)(Ws + c * Fn + f0);   // warp-uniform -> broadcast
        ulonglong2 wA = wr[0];  // pairs (f0,f0+1),(f0+2,f0+3)
        ulonglong2 wB = wr[1];  // pairs (f0+4,f0+5),(f0+6,f0+7)

        unsigned long long xp;
        xp = splat2(xv.x);
        acc[0][0] = ffma2(xp, wA.x, acc[0][0]); acc[0][1] = ffma2(xp, wA.y, acc[0][1]);
        acc[0][2] = ffma2(xp, wB.x, acc[0][2]); acc[0][3] = ffma2(xp, wB.y, acc[0][3]);
        xp = splat2(xv.y);
        acc[1][0] = ffma2(xp, wA.x, acc[1][0]); acc[1][1] = ffma2(xp, wA.y, acc[1][1]);
        acc[1][2] = ffma2(xp, wB.x, acc[1][2]); acc[1][3] = ffma2(xp, wB.y, acc[1][3]);
        xp = splat2(xv.z);
        acc[2][0] = ffma2(xp, wA.x, acc[2][0]); acc[2][1] = ffma2(xp, wA.y, acc[2][1]);
        acc[2][2] = ffma2(xp, wB.x, acc[2][2]); acc[2][3] = ffma2(xp, wB.y, acc[2][3]);
        xp = splat2(xv.w);
        acc[3][0] = ffma2(xp, wA.x, acc[3][0]); acc[3][1] = ffma2(xp, wA.y, acc[3][1]);
        acc[3][2] = ffma2(xp, wB.x, acc[3][2]); acc[3][3] = ffma2(xp, wB.y, acc[3][3]);
    }

    // ---- spill Wh to smem in [f][v] layout (conflict-free STS rows) ----
    #pragma unroll
    for (int j = 0; j < 4; j++) {
        #pragma unroll
        for (int i = 0; i < 4; i++) {
            float2 p = unpack2(acc[i][j]);
            Whs[(f0 + 2 * j)     * Vn + v0 + i] = p.x;
            Whs[(f0 + 2 * j + 1) * Vn + v0 + i] = p.y;
        }
    }
    __syncthreads();

    // ---- s1[v], s2[v] ----
    if (tid < Vn) {
        float s1 = 0.f, s2 = 0.f;
        #pragma unroll 8
        for (int f = 0; f < Fn; f++) {
            float wh = Whs[f * Vn + tid];
            s1 += wh * smem[OFF_A1 + f];
            s2 += wh * smem[OFF_A2 + f];
        }
        smem[OFF_S1 + tid] = s1;
        smem[OFF_S2 + tid] = s2;
    }
    __syncthreads();

    // ---- softmax denominator: den[v] = sum_j exp(L(s1[v] + s2[j])) ----
    {
        const int v = tid & 127, half = tid >> 7;
        float s1v = smem[OFF_S1 + v];
        float den = 0.f;
        const int j0 = half * 64;
        #pragma unroll 8
        for (int j = j0; j < j0 + 64; j++) {
            float e = s1v + smem[OFF_S2 + j];
            e = (e > 0.f) ? e : ALPHA * e;
            den += __expf(e);
        }
        smem[OFF_DENP + half * 128 + v] = den;
    }
    __syncthreads();
    if (tid < Vn) {
        float den = smem[OFF_DENP + tid] + smem[OFF_DENP + 128 + tid];
        float e = smem[OFF_S1 + tid] + smem[OFF_S2 + tid];
        e = (e > 0.f) ? e : ALPHA * e;
        smem[OFF_DIAG + tid] = __expf(e) / den;
    }
    __syncthreads();

    // ---- output: out[b][f][t][v] = elu(diag[v] * Wh[f][v]) ; STG.128 coalesced ----
    {
        const int lane = tid & 31, warp = tid >> 5;
        float4 dg = ((const float4*)(smem + OFF_DIAG))[lane];
        #pragma unroll
        for (int f = warp; f < Fn; f += 8) {
            float4 wh = ((const float4*)(Whs + f * Vn))[lane];
            float4 r;
            r.x = dg.x * wh.x; r.y = dg.y * wh.y;
            r.z = dg.z * wh.z; r.w = dg.w * wh.w;
            r.x = (r.x > 0.f) ? r.x : expm1f(r.x);
            r.y = (r.y > 0.f) ? r.y : expm1f(r.y);
            r.z = (r.z > 0.f) ? r.z : expm1f(r.z);
            r.w = (r.w > 0.f) ? r.w : expm1f(r.w);
            ((float4*)(out + ((size_t)(b * Fn + f) * Tn + t) * Vn))[lane] = r;
        }
    }
}

extern "C" void kernel_launch(void* const* d_in, const int* in_sizes, int n_in,
                              void* d_out, int out_size)
{
    const float* x = (const float*)d_in[0];
    const float* W = (const float*)d_in[1];
    const float* a = (const float*)d_in[2];
    float* out = (float*)d_out;

    cudaFuncSetAttribute(GraphAttentionLayer4D_78082505441863_kernel,
                         cudaFuncAttributeMaxDynamicSharedMemorySize,
                         SMEM_FLOATS * (int)sizeof(float));

    dim3 grid(Tn, Bn);           // one CTA per (t, b): 2048 CTAs
    GraphAttentionLayer4D_78082505441863_kernel
        <<<grid, 256, SMEM_FLOATS * sizeof(float)>>>(x, W, a, out);
}

// round 4
// speedup vs baseline: 1.1110x; 1.1110x over previous
#include <cuda_runtime.h>

// out[b][f][t][v] = elu(diag[b,v,t] * Wh[b,v,t,f])
//   Wh[b,v,t,f] = sum_c x[b,c,t,v] * W[c,f]
//   s1[v] = Wh[v,:]·a1 ; s2[v] = Wh[v,:]·a2   (per b,t)
//   diag[v] = exp(L(s1[v]+s2[v])) / sum_j exp(L(s1[v]+s2[j])),  L = leaky(0.2)

#define ALPHA 0.2f
constexpr int Bn = 8, Cn = 64, Tn = 256, Vn = 128, Fn = 64;

// ---- f32x2 packed FMA helpers ----
__device__ __forceinline__ unsigned long long ffma2(unsigned long long a,
                                                    unsigned long long b,
                                                    unsigned long long c) {
    unsigned long long d;
    asm("fma.rn.f32x2 %0, %1, %2, %3;" : "=l"(d) : "l"(a), "l"(b), "l"(c));
    return d;
}
__device__ __forceinline__ unsigned long long splat2(float x) {
    unsigned long long d;
    asm("mov.b64 %0, {%1, %1};" : "=l"(d) : "f"(x));
    return d;
}
__device__ __forceinline__ float2 unpack2(unsigned long long v) {
    float2 p;
    asm("mov.b64 {%0, %1}, %2;" : "=f"(p.x), "=f"(p.y) : "l"(v));
    return p;
}

// ---- smem layout (floats). Two overlay regions: ----
//   region A [0, 4096):     W[c][f] during GEMM; softmax scratch after
//   region B [4096, 12288): xs[c][v] during GEMM; Whs[f][v] after
#define OFF_WS    0
#define OFF_S1P   0        // s1 partials [8][128]  (overlay on Ws)
#define OFF_S2P   1024     // s2 partials [8][128]
#define OFF_DENP  2048     // den partials [2][128]
#define OFF_DIAG  2304     // diag[v] 128
#define OFF_XS    4096
#define OFF_WHS   4096     // Wh[f][v]  64*128  (overlay on xs)
#define OFF_A1    12288    // 64
#define OFF_A2    12352    // 64
#define OFF_S1    12416    // 128
#define OFF_S2    12544    // 128
#define SMEM_FLOATS 12672  // 50,688 bytes

extern __shared__ float smem[];

__global__ __launch_bounds__(256, 3)
void GraphAttentionLayer4D_78082505441863_kernel(
    const float* __restrict__ x, const float* __restrict__ W,
    const float* __restrict__ a, float* __restrict__ out)
{
    const int t   = blockIdx.x;
    const int b   = blockIdx.y;
    const int tid = threadIdx.x;

    float* Ws  = smem + OFF_WS;
    float* xs  = smem + OFF_XS;
    float* Whs = smem + OFF_WHS;

    // ---- stage W (16KB, L2-resident across CTAs) ----
    {
        const float4* Wg  = (const float4*)W;
        float4*       Ws4 = (float4*)Ws;
        #pragma unroll
        for (int i = tid; i < (Cn * Fn) / 4; i += 256) Ws4[i] = Wg[i];
    }
    // ---- stage x slice x[b, :, t, :] -> xs[c][v] (coalesced 512B rows) ----
    {
        const float4* xg  = (const float4*)x;
        float4*       xs4 = (float4*)xs;
        #pragma unroll
        for (int i = tid; i < (Cn * Vn) / 4; i += 256) {
            int c = i >> 5, v4 = i & 31;
            xs4[i] = xg[((size_t)(b * Cn + c) * Tn + t) * (Vn / 4) + v4];
        }
    }
    if (tid < 128) {
        float av = a[tid];
        if (tid < 64) smem[OFF_A1 + tid] = av;
        else          smem[OFF_A2 + tid - 64] = av;
    }
    __syncthreads();

    // ---- GEMM: Wh[v][f] = sum_c xs[c][v] * Ws[c][f] ----
    // 32 v-threads x 8 f-threads; each thread 4v x 8f, f packed into f32x2.
    const int vt = tid & 31, ft = tid >> 5;
    const int v0 = vt * 4,  f0 = ft * 8;

    unsigned long long acc[4][4];
    #pragma unroll
    for (int i = 0; i < 4; i++)
        #pragma unroll
        for (int j = 0; j < 4; j++) acc[i][j] = 0ull;

    #pragma unroll 8
    for (int c = 0; c < Cn; c++) {
        float4 xv = *(const float4*)(xs + c * Vn + v0);               // LDS.128 conflict-free
        const ulonglong2* wr = (const ulonglong2*)(Ws + c * Fn + f0); // warp-uniform broadcast
        ulonglong2 wA = wr[0];
        ulonglong2 wB = wr[1];

        unsigned long long xp;
        xp = splat2(xv.x);
        acc[0][0] = ffma2(xp, wA.x, acc[0][0]); acc[0][1] = ffma2(xp, wA.y, acc[0][1]);
        acc[0][2] = ffma2(xp, wB.x, acc[0][2]); acc[0][3] = ffma2(xp, wB.y, acc[0][3]);
        xp = splat2(xv.y);
        acc[1][0] = ffma2(xp, wA.x, acc[1][0]); acc[1][1] = ffma2(xp, wA.y, acc[1][1]);
        acc[1][2] = ffma2(xp, wB.x, acc[1][2]); acc[1][3] = ffma2(xp, wB.y, acc[1][3]);
        xp = splat2(xv.z);
        acc[2][0] = ffma2(xp, wA.x, acc[2][0]); acc[2][1] = ffma2(xp, wA.y, acc[2][1]);
        acc[2][2] = ffma2(xp, wB.x, acc[2][2]); acc[2][3] = ffma2(xp, wB.y, acc[2][3]);
        xp = splat2(xv.w);
        acc[3][0] = ffma2(xp, wA.x, acc[3][0]); acc[3][1] = ffma2(xp, wA.y, acc[3][1]);
        acc[3][2] = ffma2(xp, wB.x, acc[3][2]); acc[3][3] = ffma2(xp, wB.y, acc[3][3]);
    }
    __syncthreads();   // all xs/Ws reads done -> safe to overlay both regions

    // ---- spill Wh to smem [f][v] (into old xs region) ----
    #pragma unroll
    for (int j = 0; j < 4; j++) {
        #pragma unroll
        for (int i = 0; i < 4; i++) {
            float2 p = unpack2(acc[i][j]);
            Whs[(f0 + 2 * j)     * Vn + v0 + i] = p.x;
            Whs[(f0 + 2 * j + 1) * Vn + v0 + i] = p.y;
        }
    }
    // ---- s1/s2 partials straight from register accumulators ----
    {
        const ulonglong2* a1p = (const ulonglong2*)(smem + OFF_A1 + f0); // warp-uniform
        const ulonglong2* a2p = (const ulonglong2*)(smem + OFF_A2 + f0);
        ulonglong2 a1A = a1p[0], a1B = a1p[1];
        ulonglong2 a2A = a2p[0], a2B = a2p[1];
        #pragma unroll
        for (int i = 0; i < 4; i++) {
            unsigned long long p1 = 0ull, p2 = 0ull;
            p1 = ffma2(acc[i][0], a1A.x, p1); p1 = ffma2(acc[i][1], a1A.y, p1);
            p1 = ffma2(acc[i][2], a1B.x, p1); p1 = ffma2(acc[i][3], a1B.y, p1);
            p2 = ffma2(acc[i][0], a2A.x, p2); p2 = ffma2(acc[i][1], a2A.y, p2);
            p2 = ffma2(acc[i][2], a2B.x, p2); p2 = ffma2(acc[i][3], a2B.y, p2);
            float2 q1 = unpack2(p1), q2 = unpack2(p2);
            smem[OFF_S1P + ft * Vn + v0 + i] = q1.x + q1.y;
            smem[OFF_S2P + ft * Vn + v0 + i] = q2.x + q2.y;
        }
    }
    __syncthreads();

    // ---- reduce partials across the 8 f-groups ----
    if (tid < 128) {
        float s = 0.f;
        #pragma unroll
        for (int k = 0; k < 8; k++) s += smem[OFF_S1P + k * Vn + tid];
        smem[OFF_S1 + tid] = s;
    } else {
        int v = tid - 128;
        float s = 0.f;
        #pragma unroll
        for (int k = 0; k < 8; k++) s += smem[OFF_S2P + k * Vn + v];
        smem[OFF_S2 + v] = s;
    }
    __syncthreads();

    // ---- softmax denominator: den[v] = sum_j exp(L(s1[v] + s2[j])) ----
    {
        const int v = tid & 127, half = tid >> 7;
        float s1v = smem[OFF_S1 + v];
        float den = 0.f;
        const int j0 = half * 64;
        #pragma unroll 8
        for (int j = j0; j < j0 + 64; j++) {
            float e = s1v + smem[OFF_S2 + j];
            e = (e > 0.f) ? e : ALPHA * e;
            den += __expf(e);
        }
        smem[OFF_DENP + half * 128 + v] = den;
    }
    __syncthreads();
    if (tid < Vn) {
        float den = smem[OFF_DENP + tid] + smem[OFF_DENP + 128 + tid];
        float e = smem[OFF_S1 + tid] + smem[OFF_S2 + tid];
        e = (e > 0.f) ? e : ALPHA * e;
        smem[OFF_DIAG + tid] = __expf(e) / den;
    }
    __syncthreads();

    // ---- output: out[b][f][t][v] = elu(diag[v] * Wh[f][v]) ; STG.128 ----
    {
        const int lane = tid & 31, warp = tid >> 5;
        float4 dg = ((const float4*)(smem + OFF_DIAG))[lane];
        #pragma unroll
        for (int f = warp; f < Fn; f += 8) {
            float4 wh = ((const float4*)(Whs + f * Vn))[lane];
            float4 r;
            r.x = dg.x * wh.x; r.y = dg.y * wh.y;
            r.z = dg.z * wh.z; r.w = dg.w * wh.w;
            r.x = (r.x > 0.f) ? r.x : expm1f(r.x);
            r.y = (r.y > 0.f) ? r.y : expm1f(r.y);
            r.z = (r.z > 0.f) ? r.z : expm1f(r.z);
            r.w = (r.w > 0.f) ? r.w : expm1f(r.w);
            ((float4*)(out + ((size_t)(b * Fn + f) * Tn + t) * Vn))[lane] = r;
        }
    }
}

extern "C" void kernel_launch(void* const* d_in, const int* in_sizes, int n_in,
                              void* d_out, int out_size)
{
    const float* x = (const float*)d_in[0];
    const float* W = (const float*)d_in[1];
    const float* a = (const float*)d_in[2];
    float* out = (float*)d_out;

    cudaFuncSetAttribute(GraphAttentionLayer4D_78082505441863_kernel,
                         cudaFuncAttributeMaxDynamicSharedMemorySize,
                         SMEM_FLOATS * (int)sizeof(float));

    dim3 grid(Tn, Bn);   // one CTA per (t, b): 2048 CTAs
    GraphAttentionLayer4D_78082505441863_kernel
        <<<grid, 256, SMEM_FLOATS * sizeof(float)>>>(x, W, a, out);
}

// round 6
// speedup vs baseline: 1.3965x; 1.2569x over previous
#include <cuda_runtime.h>

// out[b][f][t][v] = elu(diag[b,v,t] * Wh[b,v,t,f])
//   Wh[b,v,t,f] = sum_c x[b,c,t,v] * W[c,f]      <-- mma.sync bf16 3-pass split
//   s1[v] = Wh[v,:]·a1 ; s2[v] = Wh[v,:]·a2       (per b,t)
//   diag[v] = exp(L(s1+s2_diag)) / sum_j exp(L(s1[v]+s2[j])),  L = leaky(0.2)

#define ALPHA 0.2f
#define LOG2E 1.4426950408889634f
constexpr int Bn = 8, Cn = 64, Tn = 256, Vn = 128, Fn = 64;

__device__ __forceinline__ unsigned smem_u32(const void* p) {
    unsigned a;
    asm("{ .reg .u64 t; cvta.to.shared.u64 t, %1; cvt.u32.u64 %0, t; }" : "=r"(a) : "l"(p));
    return a;
}
// pack two f32 -> bf16x2 (rn): result[15:0]=first arg, [31:16]=second arg
__device__ __forceinline__ unsigned pack_bf16(float lo_elem, float hi_elem) {
    unsigned r;
    asm("cvt.rn.bf16x2.f32 %0, %1, %2;" : "=r"(r) : "f"(hi_elem), "f"(lo_elem));
    return r;
}
__device__ __forceinline__ void ldsm4(unsigned* r, unsigned addr) {
    asm volatile("ldmatrix.sync.aligned.m8n8.x4.shared.b16 {%0,%1,%2,%3}, [%4];"
                 : "=r"(r[0]), "=r"(r[1]), "=r"(r[2]), "=r"(r[3]) : "r"(addr));
}
__device__ __forceinline__ void mma_bf16(float* c, const unsigned* a, const unsigned* b) {
    asm volatile(
        "mma.sync.aligned.m16n8k16.row.col.f32.bf16.bf16.f32 "
        "{%0,%1,%2,%3}, {%4,%5,%6,%7}, {%8,%9}, {%0,%1,%2,%3};"
        : "+f"(c[0]), "+f"(c[1]), "+f"(c[2]), "+f"(c[3])
        : "r"(a[0]), "r"(a[1]), "r"(a[2]), "r"(a[3]), "r"(b[0]), "r"(b[1]));
}
__device__ __forceinline__ unsigned bf16_bits(float f) {   // rn f32->bf16 bits
    unsigned u = __float_as_uint(f);
    return (u + 0x7FFFu + ((u >> 16) & 1u)) >> 16;
}

// ---- prep: W[c][f] f32 -> swizzled bf16 W^T images [f][c] (hi, lo) ----
// row f: 64 c * 2B = 128B; byte off = f*128 + ((2c) ^ ((f&7)<<4))
__device__ unsigned char g_WThi[Fn * 128];
__device__ unsigned char g_WTlo[Fn * 128];

__global__ __launch_bounds__(256) void prep_kernel(const float* __restrict__ W) {
    for (int idx = threadIdx.x; idx < Fn * Cn; idx += 256) {
        int f = idx >> 6, c = idx & 63;
        float w = W[c * Fn + f];
        unsigned hb = bf16_bits(w);
        float lo = w - __uint_as_float(hb << 16);
        unsigned lb = bf16_bits(lo);
        unsigned off = f * 128 + ((2 * c) ^ ((f & 7) << 4));
        *(unsigned short*)(g_WThi + off) = (unsigned short)hb;
        *(unsigned short*)(g_WTlo + off) = (unsigned short)lb;
    }
}

// ---- smem layout (float offsets) ----
#define OFF_A1    0      // 64
#define OFF_A2    64     // 64
#define OFF_S1    128    // 128  (scaled by log2e)
#define OFF_S2    256    // 128  (scaled by log2e)
#define OFF_S1P   384    // [2][128]
#define OFF_S2P   640    // [2][128]
#define OFF_DENP  896    // [2][128]
#define OFF_DIAG  1152   // 128
#define OFF_AHI   1280   // 16KB: A_hi [v=128][c=64] bf16 swizzled (4096 floats)
#define OFF_ALO   5376   // 16KB
#define OFF_WTHI  9472   // 8KB:  WT_hi [f=64][c=64] bf16 swizzled (2048 floats)
#define OFF_WTLO  11520  // 8KB
#define SMEM_FLOATS 13568   // 54,272 bytes

extern __shared__ float smem[];

__global__ __launch_bounds__(256, 3)
void GraphAttentionLayer4D_78082505441863_kernel(
    const float* __restrict__ x, const float* __restrict__ a,
    float* __restrict__ out)
{
    const int t    = blockIdx.x;
    const int b    = blockIdx.y;
    const int tid  = threadIdx.x;
    const int wid  = tid >> 5, lane = tid & 31;
    const int g    = lane >> 2, ti = lane & 3;   // mma quad layout
    const unsigned sbase = smem_u32(smem);

    // ---- stage WT tiles (pre-swizzled byte images, 16KB) ----
    {
        const uint4* sh = (const uint4*)g_WThi;
        const uint4* sl = (const uint4*)g_WTlo;
        uint4* dh = (uint4*)(smem + OFF_WTHI);
        uint4* dl = (uint4*)(smem + OFF_WTLO);
        #pragma unroll
        for (int i = tid; i < 512; i += 256) { dh[i] = sh[i]; dl[i] = sl[i]; }
    }
    if (tid < 128) {
        float av = a[tid];
        if (tid < 64) smem[OFF_A1 + tid] = av;
        else          smem[OFF_A2 + tid - 64] = av;
    }

    // ---- fused load+split: x[b,c,t,v] -> A_hi/A_lo [v][c] bf16 swizzled ----
    // thread: v = tid&127, c-half = (tid>>7)*32 ; gmem reads coalesced over v
    {
        const int v  = tid & 127;
        const int c0 = (tid >> 7) << 5;
        const float* xp = x + ((size_t)b * Cn + c0) * (size_t)(Tn * Vn)
                            + (size_t)t * Vn + v;
        char* Ahi = (char*)smem + OFF_AHI * 4 + v * 128;
        char* Alo = (char*)smem + OFF_ALO * 4 + v * 128;
        const unsigned sw = (v & 7) << 4;
        #pragma unroll
        for (int k = 0; k < 8; k++) {
            int c = c0 + 4 * k;
            float f0 = xp[(size_t)(4 * k + 0) * (Tn * Vn)];
            float f1 = xp[(size_t)(4 * k + 1) * (Tn * Vn)];
            float f2 = xp[(size_t)(4 * k + 2) * (Tn * Vn)];
            float f3 = xp[(size_t)(4 * k + 3) * (Tn * Vn)];
            unsigned h0 = pack_bf16(f0, f1);
            unsigned h1 = pack_bf16(f2, f3);
            float l0 = f0 - __uint_as_float(h0 << 16);
            float l1 = f1 - __uint_as_float(h0 & 0xFFFF0000u);
            float l2 = f2 - __uint_as_float(h1 << 16);
            float l3 = f3 - __uint_as_float(h1 & 0xFFFF0000u);
            unsigned q0 = pack_bf16(l0, l1);
            unsigned q1 = pack_bf16(l2, l3);
            unsigned off = (unsigned)(2 * c) ^ sw;   // 8B-aligned (2c%16 in {0,8})
            *(uint2*)(Ahi + off) = make_uint2(h0, h1);
            *(uint2*)(Alo + off) = make_uint2(q0, q1);
        }
    }
    __syncthreads();

    // ---- MMA mainloop: D[v=128][f=64] += A*B over 3 split passes ----
    // warp tile: wm = wid&3 -> vbase 32*wm ; wn = wid>>2 -> fbase 32*wn
    const int wm = wid & 3, wn = wid >> 2;
    const int vbase = wm * 32, fbase = wn * 32;

    const unsigned Ahi_s  = sbase + OFF_AHI * 4;
    const unsigned Alo_s  = sbase + OFF_ALO * 4;
    const unsigned WThi_s = sbase + OFF_WTHI * 4;
    const unsigned WTlo_s = sbase + OFF_WTLO * 4;

    // ldmatrix lane addressing (q = lane>>3, r = lane&7)
    const unsigned q = lane >> 3, r = lane & 7;
    const unsigned rA   = vbase + (q & 1) * 8 + r;       // A rows (m16 x k16 tile)
    const unsigned cAq  = (q >> 1) * 16;
    const unsigned swA  = (rA & 7) << 4;
    const unsigned rB   = fbase + (q >> 1) * 8 + r;      // WT rows (n16 x k16 tile)
    const unsigned cBq  = (q & 1) * 16;
    const unsigned swB  = (rB & 7) << 4;

    float acc[2][4][4];
    #pragma unroll
    for (int i = 0; i < 2; i++)
        #pragma unroll
        for (int j = 0; j < 4; j++)
            #pragma unroll
            for (int e = 0; e < 4; e++) acc[i][j][e] = 0.f;

    #pragma unroll
    for (int ks = 0; ks < 4; ks++) {
        const unsigned cA = (32 * ks + cAq) ^ swA;
        const unsigned cB = (32 * ks + cBq) ^ swB;
        unsigned bh[8], bl[8], af[8];
        ldsm4(bh + 0, WThi_s + rB * 128 + cB);
        ldsm4(bh + 4, WThi_s + (rB + 16) * 128 + cB);
        ldsm4(bl + 0, WTlo_s + rB * 128 + cB);
        ldsm4(bl + 4, WTlo_s + (rB + 16) * 128 + cB);
        ldsm4(af + 0, Ahi_s + rA * 128 + cA);
        ldsm4(af + 4, Ahi_s + (rA + 16) * 128 + cA);
        #pragma unroll
        for (int i = 0; i < 2; i++)
            #pragma unroll
            for (int j = 0; j < 4; j++) {
                mma_bf16(acc[i][j], af + 4 * i, bh + 2 * j);   // hi*hi
                mma_bf16(acc[i][j], af + 4 * i, bl + 2 * j);   // hi*lo
            }
        ldsm4(af + 0, Alo_s + rA * 128 + cA);
        ldsm4(af + 4, Alo_s + (rA + 16) * 128 + cA);
        #pragma unroll
        for (int i = 0; i < 2; i++)
            #pragma unroll
            for (int j = 0; j < 4; j++)
                mma_bf16(acc[i][j], af + 4 * i, bh + 2 * j);   // lo*hi
    }

    // Accumulator element (i,j,e): v = vbase+16i+g+8*(e>>1), f = fbase+8j+2ti+(e&1)

    // ---- s1/s2 partials from accumulators + quad butterfly reduce ----
    {
        float s1r[4] = {0.f, 0.f, 0.f, 0.f};
        float s2r[4] = {0.f, 0.f, 0.f, 0.f};
        #pragma unroll
        for (int j = 0; j < 4; j++) {
            float w1a = smem[OFF_A1 + fbase + 8 * j + 2 * ti];
            float w1b = smem[OFF_A1 + fbase + 8 * j + 2 * ti + 1];
            float w2a = smem[OFF_A2 + fbase + 8 * j + 2 * ti];
            float w2b = smem[OFF_A2 + fbase + 8 * j + 2 * ti + 1];
            #pragma unroll
            for (int i = 0; i < 2; i++) {
                s1r[2 * i]     += acc[i][j][0] * w1a + acc[i][j][1] * w1b;
                s1r[2 * i + 1] += acc[i][j][2] * w1a + acc[i][j][3] * w1b;
                s2r[2 * i]     += acc[i][j][0] * w2a + acc[i][j][1] * w2b;
                s2r[2 * i + 1] += acc[i][j][2] * w2a + acc[i][j][3] * w2b;
            }
        }
        #pragma unroll
        for (int k = 0; k < 4; k++) {
            s1r[k] += __shfl_xor_sync(0xFFFFFFFFu, s1r[k], 1);
            s1r[k] += __shfl_xor_sync(0xFFFFFFFFu, s1r[k], 2);
            s2r[k] += __shfl_xor_sync(0xFFFFFFFFu, s2r[k], 1);
            s2r[k] += __shfl_xor_sync(0xFFFFFFFFu, s2r[k], 2);
        }
        if (ti == 0) {
            #pragma unroll
            for (int k = 0; k < 4; k++)
                smem[OFF_S1P + wn * 128 + vbase + 16 * (k >> 1) + 8 * (k & 1) + g] = s1r[k];
        } else if (ti == 1) {
            #pragma unroll
            for (int k = 0; k < 4; k++)
                smem[OFF_S2P + wn * 128 + vbase + 16 * (k >> 1) + 8 * (k & 1) + g] = s2r[k];
        }
    }
    __syncthreads();
    // reduce the two f-half planes; pre-scale by log2e (leaky is pos-homogeneous)
    if (tid < 128) {
        smem[OFF_S1 + tid] = (smem[OFF_S1P + tid] + smem[OFF_S1P + 128 + tid]) * LOG2E;
    } else {
        int vv = tid - 128;
        smem[OFF_S2 + vv] = (smem[OFF_S2P + vv] + smem[OFF_S2P + 128 + vv]) * LOG2E;
    }
    __syncthreads();

    // ---- den[v] = sum_j exp2(leaky(s1'[v] + s2'[j])) ----
    {
        const int vv = tid & 127, half = tid >> 7;
        float s1v = smem[OFF_S1 + vv];
        float den = 0.f;
        const float4* s2v = (const float4*)(smem + OFF_S2) + half * 16;
        #pragma unroll 4
        for (int j = 0; j < 16; j++) {
            float4 s2q = s2v[j];
            float e0 = s1v + s2q.x, e1 = s1v + s2q.y;
            float e2 = s1v + s2q.z, e3 = s1v + s2q.w;
            den += exp2f(fmaxf(e0, ALPHA * e0)) + exp2f(fmaxf(e1, ALPHA * e1))
                 + exp2f(fmaxf(e2, ALPHA * e2)) + exp2f(fmaxf(e3, ALPHA * e3));
        }
        smem[OFF_DENP + half * 128 + vv] = den;
    }
    __syncthreads();
    if (tid < 128) {
        float den = smem[OFF_DENP + tid] + smem[OFF_DENP + 128 + tid];
        float e = smem[OFF_S1 + tid] + smem[OFF_S2 + tid];
        smem[OFF_DIAG + tid] = exp2f(fmaxf(e, ALPHA * e)) / den;
    }
    __syncthreads();

    // ---- out[b][f][t][v] = elu(diag[v] * acc) ; 32B-contiguous STG.32 ----
    {
        float dg[4];
        #pragma unroll
        for (int k = 0; k < 4; k++)
            dg[k] = smem[OFF_DIAG + vbase + 16 * (k >> 1) + 8 * (k & 1) + g];
        #pragma unroll
        for (int i = 0; i < 2; i++) {
            const int v0 = vbase + 16 * i + g;
            #pragma unroll
            for (int j = 0; j < 4; j++) {
                const int f = fbase + 8 * j + 2 * ti;
                float* ob = out + ((size_t)(b * Fn + f) * Tn + t) * Vn;
                float r0 = dg[2 * i]     * acc[i][j][0];
                float r1 = dg[2 * i]     * acc[i][j][1];
                float r2 = dg[2 * i + 1] * acc[i][j][2];
                float r3 = dg[2 * i + 1] * acc[i][j][3];
                r0 = (r0 > 0.f) ? r0 : expm1f(r0);
                r1 = (r1 > 0.f) ? r1 : expm1f(r1);
                r2 = (r2 > 0.f) ? r2 : expm1f(r2);
                r3 = (r3 > 0.f) ? r3 : expm1f(r3);
                ob[v0]            = r0;
                ob[Tn * Vn + v0]  = r1;          // f+1
                ob[v0 + 8]        = r2;
                ob[Tn * Vn + v0 + 8] = r3;       // f+1
            }
        }
    }
}

extern "C" void kernel_launch(void* const* d_in, const int* in_sizes, int n_in,
                              void* d_out, int out_size)
{
    const float* x = (const float*)d_in[0];
    const float* W = (const float*)d_in[1];
    const float* a = (const float*)d_in[2];
    float* out = (float*)d_out;

    cudaFuncSetAttribute(GraphAttentionLayer4D_78082505441863_kernel,
                         cudaFuncAttributeMaxDynamicSharedMemorySize,
                         SMEM_FLOATS * (int)sizeof(float));

    prep_kernel<<<1, 256>>>(W);

    dim3 grid(Tn, Bn);   // one CTA per (t, b): 2048 CTAs
    GraphAttentionLayer4D_78082505441863_kernel
        <<<grid, 256, SMEM_FLOATS * sizeof(float)>>>(x, a, out);
}

// round 7
// speedup vs baseline: 1.5795x; 1.1311x over previous
#include <cuda_runtime.h>

// out[b][f][t][v] = elu(diag[b,v,t] * Wh[b,v,t,f])
//   Wh[b,v,t,f] = sum_c x[b,c,t,v] * W[c,f]      <-- mma.sync bf16 3-pass split
//   s1[v] = Wh[v,:]·a1 ; s2[v] = Wh[v,:]·a2       (per b,t)
//   diag[v] = exp(L(s1+s2_diag)) / sum_j exp(L(s1[v]+s2[j])),  L = leaky(0.2)

#define ALPHA 0.2f
#define LOG2E 1.4426950408889634f
constexpr int Bn = 8, Cn = 64, Tn = 256, Vn = 128, Fn = 64;

__device__ __forceinline__ unsigned smem_u32(const void* p) {
    unsigned a;
    asm("{ .reg .u64 t; cvta.to.shared.u64 t, %1; cvt.u32.u64 %0, t; }" : "=r"(a) : "l"(p));
    return a;
}
// pack two f32 -> bf16x2 (rn): result[15:0]=first arg, [31:16]=second arg
__device__ __forceinline__ unsigned pack_bf16(float lo_elem, float hi_elem) {
    unsigned r;
    asm("cvt.rn.bf16x2.f32 %0, %1, %2;" : "=r"(r) : "f"(hi_elem), "f"(lo_elem));
    return r;
}
__device__ __forceinline__ void ldsm4(unsigned* r, unsigned addr) {
    asm volatile("ldmatrix.sync.aligned.m8n8.x4.shared.b16 {%0,%1,%2,%3}, [%4];"
                 : "=r"(r[0]), "=r"(r[1]), "=r"(r[2]), "=r"(r[3]) : "r"(addr));
}
__device__ __forceinline__ void mma_bf16(float* c, const unsigned* a, const unsigned* b) {
    asm volatile(
        "mma.sync.aligned.m16n8k16.row.col.f32.bf16.bf16.f32 "
        "{%0,%1,%2,%3}, {%4,%5,%6,%7}, {%8,%9}, {%0,%1,%2,%3};"
        : "+f"(c[0]), "+f"(c[1]), "+f"(c[2]), "+f"(c[3])
        : "r"(a[0]), "r"(a[1]), "r"(a[2]), "r"(a[3]), "r"(b[0]), "r"(b[1]));
}
__device__ __forceinline__ unsigned bf16_bits(float f) {   // rn f32->bf16 bits
    unsigned u = __float_as_uint(f);
    return (u + 0x7FFFu + ((u >> 16) & 1u)) >> 16;
}
// branchless ELU: r>0 -> r ; small-neg -> cubic ; else exp2-based
__device__ __forceinline__ float elu_fast(float r) {
    float em  = exp2f(r * LOG2E) - 1.0f;
    float pl  = r * fmaf(r, fmaf(r, 0.16666667f, 0.5f), 1.0f);
    float neg = (r > -0.03125f) ? pl : em;
    return (r > 0.f) ? r : neg;
}

// ---- prep: W[c][f] f32 -> swizzled bf16 W^T images [f][c] (hi, lo) ----
// row f: 64 c * 2B = 128B; byte off = f*128 + ((2c) ^ ((f&7)<<4))
__device__ unsigned char g_WThi[Fn * 128];
__device__ unsigned char g_WTlo[Fn * 128];

__global__ __launch_bounds__(256) void prep_kernel(const float* __restrict__ W) {
    for (int idx = threadIdx.x; idx < Fn * Cn; idx += 256) {
        int f = idx >> 6, c = idx & 63;
        float w = W[c * Fn + f];
        unsigned hb = bf16_bits(w);
        float lo = w - __uint_as_float(hb << 16);
        unsigned lb = bf16_bits(lo);
        unsigned off = f * 128 + ((2 * c) ^ ((f & 7) << 4));
        *(unsigned short*)(g_WThi + off) = (unsigned short)hb;
        *(unsigned short*)(g_WTlo + off) = (unsigned short)lb;
    }
}

// ---- smem layout (float offsets) ----
#define OFF_A1    0      // 64
#define OFF_A2    64     // 64
#define OFF_S1    128    // 128  (scaled by log2e)
#define OFF_S2    256    // 128  (scaled by log2e)
#define OFF_S1P   384    // [2][128]
#define OFF_S2P   640    // [2][128]
#define OFF_DENP  896    // [2][128]
#define OFF_DIAG  1152   // 128
#define OFF_AHI   1280   // 16KB: A_hi [v=128][c=64] bf16 swizzled (4096 floats)
#define OFF_ALO   5376   // 16KB
#define OFF_WTHI  9472   // 8KB:  WT_hi [f=64][c=64] bf16 swizzled (2048 floats)
#define OFF_WTLO  11520  // 8KB
#define SMEM_FLOATS 13568   // 54,272 bytes -> 4 CTAs/SM fits in 228KB

extern __shared__ float smem[];

__global__ __launch_bounds__(256, 4)
void GraphAttentionLayer4D_78082505441863_kernel(
    const float* __restrict__ x, const float* __restrict__ a,
    float* __restrict__ out)
{
    const int t    = blockIdx.x;
    const int b    = blockIdx.y;
    const int tid  = threadIdx.x;
    const int wid  = tid >> 5, lane = tid & 31;
    const int g    = lane >> 2, ti = lane & 3;   // mma quad layout
    const unsigned sbase = smem_u32(smem);

    // ---- stage WT tiles (pre-swizzled byte images, 16KB) ----
    {
        const uint4* sh = (const uint4*)g_WThi;
        const uint4* sl = (const uint4*)g_WTlo;
        uint4* dh = (uint4*)(smem + OFF_WTHI);
        uint4* dl = (uint4*)(smem + OFF_WTLO);
        #pragma unroll
        for (int i = tid; i < 512; i += 256) { dh[i] = sh[i]; dl[i] = sl[i]; }
    }
    if (tid < 128) {
        float av = a[tid];
        if (tid < 64) smem[OFF_A1 + tid] = av;
        else          smem[OFF_A2 + tid - 64] = av;
    }

    // ---- fused load+split: x[b,c,t,v] -> A_hi/A_lo [v][c] bf16 swizzled ----
    {
        const int v  = tid & 127;
        const int c0 = (tid >> 7) << 5;
        const float* xp = x + ((size_t)b * Cn + c0) * (size_t)(Tn * Vn)
                            + (size_t)t * Vn + v;
        char* Ahi = (char*)smem + OFF_AHI * 4 + v * 128;
        char* Alo = (char*)smem + OFF_ALO * 4 + v * 128;
        const unsigned sw = (v & 7) << 4;
        #pragma unroll
        for (int k = 0; k < 8; k++) {
            int c = c0 + 4 * k;
            float f0 = xp[(size_t)(4 * k + 0) * (Tn * Vn)];
            float f1 = xp[(size_t)(4 * k + 1) * (Tn * Vn)];
            float f2 = xp[(size_t)(4 * k + 2) * (Tn * Vn)];
            float f3 = xp[(size_t)(4 * k + 3) * (Tn * Vn)];
            unsigned h0 = pack_bf16(f0, f1);
            unsigned h1 = pack_bf16(f2, f3);
            float l0 = f0 - __uint_as_float(h0 << 16);
            float l1 = f1 - __uint_as_float(h0 & 0xFFFF0000u);
            float l2 = f2 - __uint_as_float(h1 << 16);
            float l3 = f3 - __uint_as_float(h1 & 0xFFFF0000u);
            unsigned q0 = pack_bf16(l0, l1);
            unsigned q1 = pack_bf16(l2, l3);
            unsigned off = (unsigned)(2 * c) ^ sw;   // 8B-aligned
            *(uint2*)(Ahi + off) = make_uint2(h0, h1);
            *(uint2*)(Alo + off) = make_uint2(q0, q1);
        }
    }
    __syncthreads();

    // ---- MMA mainloop: D[v=128][f=64], 3 split passes, low reg pressure ----
    const int wm = wid & 3, wn = wid >> 2;
    const int vbase = wm * 32, fbase = wn * 32;

    // ldmatrix lane addressing (q = lane>>3, r = lane&7)
    const unsigned q = lane >> 3, r = lane & 7;
    const unsigned rA  = vbase + (q & 1) * 8 + r;
    const unsigned cAq = (q >> 1) * 16;
    const unsigned swA = (rA & 7) << 4;
    const unsigned rB  = fbase + (q >> 1) * 8 + r;
    const unsigned cBq = (q & 1) * 16;
    const unsigned swB = (rB & 7) << 4;     // same for rB and rB+16

    const unsigned pAhi = sbase + OFF_AHI  * 4 + rA * 128;
    const unsigned pAlo = sbase + OFF_ALO  * 4 + rA * 128;
    const unsigned pBhi = sbase + OFF_WTHI * 4 + rB * 128;
    const unsigned pBlo = sbase + OFF_WTLO * 4 + rB * 128;

    float acc[2][4][4];
    #pragma unroll
    for (int i = 0; i < 2; i++)
        #pragma unroll
        for (int j = 0; j < 4; j++)
            #pragma unroll
            for (int e = 0; e < 4; e++) acc[i][j][e] = 0.f;

    #pragma unroll
    for (int ks = 0; ks < 4; ks++) {
        const unsigned cA = (32 * ks + cAq) ^ swA;
        const unsigned cB = (32 * ks + cBq) ^ swB;
        unsigned ax[8], bx[4];
        // A = hi
        ldsm4(ax,     pAhi + cA);
        ldsm4(ax + 4, pAhi + 2048 + cA);
        // B = hi (n-half 0, then 1)
        ldsm4(bx, pBhi + cB);
        mma_bf16(acc[0][0], ax, bx);     mma_bf16(acc[0][1], ax, bx + 2);
        mma_bf16(acc[1][0], ax + 4, bx); mma_bf16(acc[1][1], ax + 4, bx + 2);
        ldsm4(bx, pBhi + 2048 + cB);
        mma_bf16(acc[0][2], ax, bx);     mma_bf16(acc[0][3], ax, bx + 2);
        mma_bf16(acc[1][2], ax + 4, bx); mma_bf16(acc[1][3], ax + 4, bx + 2);
        // B = lo
        ldsm4(bx, pBlo + cB);
        mma_bf16(acc[0][0], ax, bx);     mma_bf16(acc[0][1], ax, bx + 2);
        mma_bf16(acc[1][0], ax + 4, bx); mma_bf16(acc[1][1], ax + 4, bx + 2);
        ldsm4(bx, pBlo + 2048 + cB);
        mma_bf16(acc[0][2], ax, bx);     mma_bf16(acc[0][3], ax, bx + 2);
        mma_bf16(acc[1][2], ax + 4, bx); mma_bf16(acc[1][3], ax + 4, bx + 2);
        // A = lo, B = hi
        ldsm4(ax,     pAlo + cA);
        ldsm4(ax + 4, pAlo + 2048 + cA);
        ldsm4(bx, pBhi + cB);
        mma_bf16(acc[0][0], ax, bx);     mma_bf16(acc[0][1], ax, bx + 2);
        mma_bf16(acc[1][0], ax + 4, bx); mma_bf16(acc[1][1], ax + 4, bx + 2);
        ldsm4(bx, pBhi + 2048 + cB);
        mma_bf16(acc[0][2], ax, bx);     mma_bf16(acc[0][3], ax, bx + 2);
        mma_bf16(acc[1][2], ax + 4, bx); mma_bf16(acc[1][3], ax + 4, bx + 2);
    }

    // Accumulator element (i,j,e): v = vbase+16i+g+8*(e>>1), f = fbase+8j+2ti+(e&1)

    // ---- s1/s2 partials from accumulators + quad butterfly reduce ----
    {
        float s1r[4] = {0.f, 0.f, 0.f, 0.f};
        float s2r[4] = {0.f, 0.f, 0.f, 0.f};
        #pragma unroll
        for (int j = 0; j < 4; j++) {
            float w1a = smem[OFF_A1 + fbase + 8 * j + 2 * ti];
            float w1b = smem[OFF_A1 + fbase + 8 * j + 2 * ti + 1];
            float w2a = smem[OFF_A2 + fbase + 8 * j + 2 * ti];
            float w2b = smem[OFF_A2 + fbase + 8 * j + 2 * ti + 1];
            #pragma unroll
            for (int i = 0; i < 2; i++) {
                s1r[2 * i]     += acc[i][j][0] * w1a + acc[i][j][1] * w1b;
                s1r[2 * i + 1] += acc[i][j][2] * w1a + acc[i][j][3] * w1b;
                s2r[2 * i]     += acc[i][j][0] * w2a + acc[i][j][1] * w2b;
                s2r[2 * i + 1] += acc[i][j][2] * w2a + acc[i][j][3] * w2b;
            }
        }
        #pragma unroll
        for (int k = 0; k < 4; k++) {
            s1r[k] += __shfl_xor_sync(0xFFFFFFFFu, s1r[k], 1);
            s1r[k] += __shfl_xor_sync(0xFFFFFFFFu, s1r[k], 2);
            s2r[k] += __shfl_xor_sync(0xFFFFFFFFu, s2r[k], 1);
            s2r[k] += __shfl_xor_sync(0xFFFFFFFFu, s2r[k], 2);
        }
        if (ti == 0) {
            #pragma unroll
            for (int k = 0; k < 4; k++)
                smem[OFF_S1P + wn * 128 + vbase + 16 * (k >> 1) + 8 * (k & 1) + g] = s1r[k];
        } else if (ti == 1) {
            #pragma unroll
            for (int k = 0; k < 4; k++)
                smem[OFF_S2P + wn * 128 + vbase + 16 * (k >> 1) + 8 * (k & 1) + g] = s2r[k];
        }
    }
    __syncthreads();
    // reduce the two f-half planes; pre-scale by log2e (leaky is pos-homogeneous)
    if (tid < 128) {
        smem[OFF_S1 + tid] = (smem[OFF_S1P + tid] + smem[OFF_S1P + 128 + tid]) * LOG2E;
    } else {
        int vv = tid - 128;
        smem[OFF_S2 + vv] = (smem[OFF_S2P + vv] + smem[OFF_S2P + 128 + vv]) * LOG2E;
    }
    __syncthreads();

    // ---- den[v] = sum_j exp2(leaky(s1'[v] + s2'[j])) ----
    {
        const int vv = tid & 127, half = tid >> 7;
        float s1v = smem[OFF_S1 + vv];
        float den = 0.f;
        const float4* s2v = (const float4*)(smem + OFF_S2) + half * 16;
        #pragma unroll 4
        for (int j = 0; j < 16; j++) {
            float4 s2q = s2v[j];
            float e0 = s1v + s2q.x, e1 = s1v + s2q.y;
            float e2 = s1v + s2q.z, e3 = s1v + s2q.w;
            den += exp2f(fmaxf(e0, ALPHA * e0)) + exp2f(fmaxf(e1, ALPHA * e1))
                 + exp2f(fmaxf(e2, ALPHA * e2)) + exp2f(fmaxf(e3, ALPHA * e3));
        }
        smem[OFF_DENP + half * 128 + vv] = den;
    }
    __syncthreads();
    if (tid < 128) {
        float den = smem[OFF_DENP + tid] + smem[OFF_DENP + 128 + tid];
        float e = smem[OFF_S1 + tid] + smem[OFF_S2 + tid];
        smem[OFF_DIAG + tid] = exp2f(fmaxf(e, ALPHA * e)) / den;
    }
    __syncthreads();

    // ---- out[b][f][t][v] = elu(diag[v] * acc) ; 32B-contiguous STG.32 ----
    {
        float dg[4];
        #pragma unroll
        for (int k = 0; k < 4; k++)
            dg[k] = smem[OFF_DIAG + vbase + 16 * (k >> 1) + 8 * (k & 1) + g];
        #pragma unroll
        for (int i = 0; i < 2; i++) {
            const int v0 = vbase + 16 * i + g;
            #pragma unroll
            for (int j = 0; j < 4; j++) {
                const int f = fbase + 8 * j + 2 * ti;
                float* ob = out + ((size_t)(b * Fn + f) * Tn + t) * Vn;
                ob[v0]               = elu_fast(dg[2 * i]     * acc[i][j][0]);
                ob[Tn * Vn + v0]     = elu_fast(dg[2 * i]     * acc[i][j][1]);
                ob[v0 + 8]           = elu_fast(dg[2 * i + 1] * acc[i][j][2]);
                ob[Tn * Vn + v0 + 8] = elu_fast(dg[2 * i + 1] * acc[i][j][3]);
            }
        }
    }
}

extern "C" void kernel_launch(void* const* d_in, const int* in_sizes, int n_in,
                              void* d_out, int out_size)
{
    const float* x = (const float*)d_in[0];
    const float* W = (const float*)d_in[1];
    const float* a = (const float*)d_in[2];
    float* out = (float*)d_out;

    cudaFuncSetAttribute(GraphAttentionLayer4D_78082505441863_kernel,
                         cudaFuncAttributeMaxDynamicSharedMemorySize,
                         SMEM_FLOATS * (int)sizeof(float));

    prep_kernel<<<1, 256>>>(W);

    dim3 grid(Tn, Bn);   // one CTA per (t, b): 2048 CTAs
    GraphAttentionLayer4D_78082505441863_kernel
        <<<grid, 256, SMEM_FLOATS * sizeof(float)>>>(x, a, out);
}